// round 15
// baseline (speedup 1.0000x reference)
#include <cuda_runtime.h>
#include <cuda_fp16.h>
#include <math.h>
#include <cstdint>

#define B_ 32
#define NN 511
#define F_ 512
#define F3 1536

// ======================= scratch (static device globals) =======================
static __device__ __align__(16) float g_enode[B_ * F_];
static __device__ __align__(16) float g_eforw[B_ * F_];
static __device__ __align__(16) float g_scores[B_ * 512];
static __device__ __align__(16) float g_fe_iou[(size_t)B_ * NN * F3];
static __device__ __align__(16) float g_ff[(size_t)B_ * 255 * F_];
static __device__ __align__(16) float g_h[(size_t)B_ * NN * F_];
static __device__ __align__(16) float g_c[(size_t)B_ * NN * F_];
static __device__ __align__(16) float g_fc[(size_t)B_ * 256 * F_];
static __device__ __align__(16) float g_iou[(size_t)B_ * 128 * F3];
static __device__ __align__(16) float g_r[B_ * 512];
// fp16 activations (single precision-rounded copy)
static __device__ __align__(16) __half g_f2[(size_t)B_ * NN * F_];
static __device__ __align__(16) __half g_ha[(size_t)B_ * NN * F_];
static __device__ __align__(16) __half g_hs[(size_t)B_ * 128 * F_];
// fp16 hi/lo weights
static __device__ __align__(16) __half g_wfeiou_h[F3 * F_], g_wfeiou_l[F3 * F_];
static __device__ __align__(16) __half g_wfef_h[F_ * F_],  g_wfef_l[F_ * F_];
static __device__ __align__(16) __half g_wf_h[F_ * F_],    g_wf_l[F_ * F_];
static __device__ __align__(16) __half g_wiou_h[F3 * F_],  g_wiou_l[F3 * F_];

__device__ __forceinline__ float sigf(float x) { return 1.f / (1.f + expf(-x)); }
__device__ __forceinline__ void split_h(float x, __half& h, __half& l) {
    h = __float2half(x);
    l = __float2half(x - __half2float(h));
}

__device__ __forceinline__ uint32_t smem_u32(const void* p) {
    uint32_t a;
    asm("{ .reg .u64 t; cvta.to.shared.u64 t, %1; cvt.u32.u64 %0, t; }" : "=r"(a) : "l"(p));
    return a;
}

#define CP16(dst, src) \
    asm volatile("cp.async.cg.shared.global [%0], [%1], 16;" :: "r"(dst), "l"(src) : "memory")
#define CP_COMMIT() asm volatile("cp.async.commit_group;" ::: "memory")
template <int N>
__device__ __forceinline__ void cp_wait() {
    asm volatile("cp.async.wait_group %0;" :: "n"(N) : "memory");
}

__device__ __forceinline__ void mma16816(float* c, const uint32_t* a, const uint32_t* b) {
    asm volatile(
        "mma.sync.aligned.m16n8k16.row.col.f32.f16.f16.f32 "
        "{%0,%1,%2,%3}, {%4,%5,%6,%7}, {%8,%9}, {%0,%1,%2,%3};"
        : "+f"(c[0]), "+f"(c[1]), "+f"(c[2]), "+f"(c[3])
        : "r"(a[0]), "r"(a[1]), "r"(a[2]), "r"(a[3]), "r"(b[0]), "r"(b[1]));
}

__device__ __forceinline__ void ldsm4(uint32_t& r0, uint32_t& r1, uint32_t& r2, uint32_t& r3,
                                      uint32_t addr) {
    asm volatile("ldmatrix.sync.aligned.m8n8.x4.shared.b16 {%0,%1,%2,%3}, [%4];"
                 : "=r"(r0), "=r"(r1), "=r"(r2), "=r"(r3) : "r"(addr));
}

// ======================= prologue (weight conversion + enode/eforw fused) =======================
__global__ void prolog_k(const float* __restrict__ s0, const float* __restrict__ s1,
                         const float* __restrict__ s2, const float* __restrict__ s3,
                         const float* __restrict__ eh, const float* __restrict__ Wn,
                         const float* __restrict__ Wf) {
    int bx = blockIdx.x;
    if (bx < 8192) {
        int i = bx * 256 + threadIdx.x;  // total 2097152
        if (i < 786432) {
            split_h(s0[i], g_wfeiou_h[i], g_wfeiou_l[i]);
        } else if (i < 1048576) {
            int j = i - 786432;
            split_h(s1[j], g_wfef_h[j], g_wfef_l[j]);
        } else if (i < 1310720) {
            int j = i - 1048576;
            split_h(s2[j], g_wf_h[j], g_wf_l[j]);
        } else {
            int j = i - 1310720;
            split_h(s3[j], g_wiou_h[j], g_wiou_l[j]);
        }
    } else {
        bx -= 8192;                       // 4096 blocks: x(64) | b(32) | z(2)
        int x = bx & 63, b = (bx >> 6) & 31, z = bx >> 11;
        int warp = threadIdx.x >> 5, lane = threadIdx.x & 31;
        int j = x * 8 + warp;
        const float* W = z ? Wf : Wn;
        float* o = z ? g_eforw : g_enode;
        const float4* wr = (const float4*)(W + (size_t)j * 1024);
        const float4* er = (const float4*)(eh + (size_t)b * 1024);
        float s = 0.f;
        for (int t = lane; t < 256; t += 32) {
            float4 w = wr[t], e = er[t];
            s += w.x * e.x + w.y * e.y + w.z * e.z + w.w * e.w;
        }
        #pragma unroll
        for (int off = 16; off; off >>= 1) s += __shfl_xor_sync(0xffffffffu, s, off);
        if (!lane) o[b * F_ + j] = s;
    }
}

__global__ void scores_k(const float* __restrict__ feat) {
    int gw = (blockIdx.x * blockDim.x + threadIdx.x) >> 5;
    int lane = threadIdx.x & 31;
    if (gw >= B_ * NN) return;
    int b = gw / NN;
    const float4* fr = (const float4*)(feat + (size_t)gw * F_);
    const float4* er = (const float4*)(g_enode + b * F_);
    float s = 0.f;
    for (int t = lane; t < 128; t += 32) {
        float4 f = fr[t], e = er[t];
        s += f.x * e.x + f.y * e.y + f.z * e.z + f.w * e.w;
    }
    #pragma unroll
    for (int off = 16; off; off >>= 1) s += __shfl_xor_sync(0xffffffffu, s, off);
    if (!lane) g_scores[b * 512 + (gw - b * NN)] = s;
}

// ---------------- streaming feat2: rolling 4-row window ----------------
__global__ void __launch_bounds__(128)
feat2_k(const float* __restrict__ feat) {
    __shared__ float pr[64][4];
    const int ic = blockIdx.x, b = blockIdx.y, fch = blockIdx.z;
    const int tid = threadIdx.x;
    const int start = ic * 64;

    if (tid < 64) {
        int i = start + tid;
        if (i < NN) {
            int cnt = min(i + 3, NN - 1) - i + 1;
            float sc[4], mx = -1e30f;
            #pragma unroll
            for (int k = 0; k < 4; k++) {
                sc[k] = (k < cnt) ? g_scores[b * 512 + i + k] : -1e30f;
                mx = fmaxf(mx, sc[k]);
            }
            float sum = 0.f;
            #pragma unroll
            for (int k = 0; k < 4; k++) {
                sc[k] = (k < cnt) ? expf(sc[k] - mx) : 0.f;
                sum += sc[k];
            }
            float inv = 1.f / sum;
            #pragma unroll
            for (int k = 0; k < 4; k++) pr[tid][k] = sc[k] * inv;
        }
    }
    __syncthreads();

    const int f = fch * 128 + tid;
    const float* fb = feat + ((size_t)b * NN) * F_ + f;
    float r0 = fb[(size_t)min(start, NN - 1) * F_];
    float r1 = fb[(size_t)min(start + 1, NN - 1) * F_];
    float r2 = fb[(size_t)min(start + 2, NN - 1) * F_];
    size_t obase = ((size_t)b * NN + start) * F_ + f;
    const int nout = min(64, NN - start);
    for (int j = 0; j < nout; j++) {
        int i = start + j;
        float r3 = fb[(size_t)min(i + 3, NN - 1) * F_];
        float a = pr[j][0] * r0 + pr[j][1] * r1 + pr[j][2] * r2 + pr[j][3] * r3;
        g_f2[obase] = __float2half(a);
        obase += F_;
        r0 = r1; r1 = r2; r2 = r3;
    }
}

// ======================= HMMA GEMM core (fp16, fp32 acc) =======================
// Block tile 128x256x64, 8 warps (2M x 4N), warp tile 64x64, ldmatrix fragments.
// 2-stage cp.async pipeline (90KB/stage), 1 CTA/SM, 8 k-chunks.
// MODE 0: fe_iou = feat2 @ W_fe_iou^T + bias          (2-pass W hi/lo)
// MODE 1: ff     = feat2[parents] @ W_fe_f^T + bias   (1-pass, sigmoid-damped)
// MODE 2: fc     = sigmoid(h[child] @ W_f^T + ff[parent]) * c[child]  (1-pass)
// MODE 3: iou    = hsum @ W_iou^T + fe_iou[parent]    (2-pass W hi/lo)
#define ROWP 144
#define ATILE (128 * ROWP)               // 18432
#define BTILE (256 * ROWP)               // 36864
#define STAGE_B (ATILE + 2 * BTILE)      // 92160
#define SMEM_TOT (2 * STAGE_B)           // 184320

template <int MODE>
__device__ __forceinline__ void gemm_core(char* smem, int bm, int bn,
                                          const float* __restrict__ bias,
                                          int M, int s, int np) {
    constexpr bool TP = (MODE == 0 || MODE == 3);   // two-pass weights
    const uint32_t sb = smem_u32(smem);
    const int tid = threadIdx.x;
    const int warp = tid >> 5, lane = tid & 31;
    const int wm = warp >> 2, wn = warp & 3;        // 2M x 4N warps, 64x64 each
    const int qrow = lane >> 2, qcol = (lane & 3) * 2;

    const __half *Aa, *Wh, *Wl;
    if (MODE == 0) { Aa = g_f2; Wh = g_wfeiou_h; Wl = g_wfeiou_l; }
    else if (MODE == 1) { Aa = g_f2; Wh = g_wfef_h; Wl = g_wfef_l; }
    else if (MODE == 2) { Aa = g_ha; Wh = g_wf_h; Wl = g_wf_l; }
    else { Aa = g_hs; Wh = g_wiou_h; Wl = g_wiou_l; }

    // --- cp.async geometry ---
    const int quad = tid & 7;        // 16B group (8 per 128B row)
    const int rowb = tid >> 3;       // 0..31
    int ar[4];                       // A rows: rowb + 32j, j=0..3
    uint32_t da[4];
    #pragma unroll
    for (int j = 0; j < 4; j++) {
        int r = rowb + j * 32;
        int rA = min(bm + r, M - 1);
        int arow;
        if (MODE == 0 || MODE == 3) arow = rA;
        else if (MODE == 1) { int b0 = rA / 255; arow = b0 * NN + (rA - b0 * 255); }
        else { int two = 2 * np; int b0 = rA / two; arow = b0 * NN + 2 * s + 1 + (rA - b0 * two); }
        ar[j] = arow * F_ + quad * 8;
        da[j] = (uint32_t)(r * ROWP + quad * 16);
    }
    int wrr[8];                      // W rows: rowb + 32j, j=0..7 (256 rows)
    uint32_t dw[8];
    #pragma unroll
    for (int j = 0; j < 8; j++) {
        int r = rowb + j * 32;
        wrr[j] = (bn + r) * F_ + quad * 8;
        dw[j] = (uint32_t)(r * ROWP + quad * 16);
    }

    // --- ldmatrix lane offsets ---
    const uint32_t a_l = (uint32_t)((wm * 64 + (lane & 15)) * ROWP + (lane >> 4) * 16);
    const uint32_t b_l = (uint32_t)((wn * 64 + ((lane >> 4) & 1) * 8 + (lane & 7)) * ROWP +
                                    ((lane >> 3) & 1) * 16);

#define LOAD_CHUNK(cidx, stgi) do {                                        \
    int k0 = (cidx) * 64;                                                  \
    uint32_t s0a = sb + (stgi) * STAGE_B;                                  \
    CP16(s0a + da[0], Aa + ar[0] + k0);                                    \
    CP16(s0a + da[1], Aa + ar[1] + k0);                                    \
    CP16(s0a + da[2], Aa + ar[2] + k0);                                    \
    CP16(s0a + da[3], Aa + ar[3] + k0);                                    \
    _Pragma("unroll")                                                      \
    for (int j = 0; j < 8; j++)                                            \
        CP16(s0a + ATILE + dw[j], Wh + wrr[j] + k0);                       \
    if (TP) {                                                              \
        _Pragma("unroll")                                                  \
        for (int j = 0; j < 8; j++)                                        \
            CP16(s0a + ATILE + BTILE + dw[j], Wl + wrr[j] + k0);           \
    }                                                                      \
    CP_COMMIT();                                                          \
} while (0)

    float acc[4][8][4] = {};

    LOAD_CHUNK(0, 0);

    for (int c = 0; c < 8; c++) {
        if (c) __syncthreads();          // prior compute on the stage LOAD will overwrite is done
        if (c < 7) LOAD_CHUNK(c + 1, (c + 1) & 1);
        if (c < 7) cp_wait<1>(); else cp_wait<0>();
        __syncthreads();                 // chunk-c data visible to all threads

        const uint32_t stg = sb + (c & 1) * STAGE_B;
        #pragma unroll
        for (int kk = 0; kk < 4; kk++) {
            uint32_t ah[4][4];
            #pragma unroll
            for (int mf = 0; mf < 4; mf++) {
                ldsm4(ah[mf][0], ah[mf][1], ah[mf][2], ah[mf][3],
                      stg + a_l + mf * 2304 + kk * 32);
            }
            #pragma unroll
            for (int p = 0; p < 4; p++) {
                uint32_t bh[4], bl[4];
                uint32_t baddr = stg + ATILE + b_l + p * 2304 + kk * 32;
                ldsm4(bh[0], bh[1], bh[2], bh[3], baddr);
                if (TP) ldsm4(bl[0], bl[1], bl[2], bl[3], baddr + BTILE);
                #pragma unroll
                for (int mf = 0; mf < 4; mf++) {
                    mma16816(acc[mf][2 * p],     ah[mf], &bh[0]);
                    mma16816(acc[mf][2 * p + 1], ah[mf], &bh[2]);
                    if (TP) {
                        mma16816(acc[mf][2 * p],     ah[mf], &bl[0]);
                        mma16816(acc[mf][2 * p + 1], ah[mf], &bl[2]);
                    }
                }
            }
        }
    }
#undef LOAD_CHUNK

    // --- epilogue ---
    #pragma unroll
    for (int mf = 0; mf < 4; mf++) {
        #pragma unroll
        for (int half = 0; half < 2; half++) {
            int m = bm + wm * 64 + mf * 16 + qrow + half * 8;
            if (m >= M) continue;
            int b = 0, node = 0, p = 0;
            if (MODE == 2) {
                int two = 2 * np;
                b = m / two;
                int cl = m - b * two;
                node = 2 * s + 1 + cl;
                p = s + (cl >> 1);
            } else if (MODE == 3) {
                b = m / np;
                p = s + (m - b * np);
            }
            #pragma unroll
            for (int nf = 0; nf < 8; nf++) {
                int n = bn + wn * 64 + nf * 8 + qcol;
                float2 v = make_float2(acc[mf][nf][half * 2], acc[mf][nf][half * 2 + 1]);
                if (MODE == 0) {
                    float2 bi = *(const float2*)(bias + n);
                    v.x += bi.x; v.y += bi.y;
                    *(float2*)(g_fe_iou + (size_t)m * F3 + n) = v;
                } else if (MODE == 1) {
                    float2 bi = *(const float2*)(bias + n);
                    v.x += bi.x; v.y += bi.y;
                    *(float2*)(g_ff + (size_t)m * F_ + n) = v;
                } else if (MODE == 2) {
                    float2 ffv = *(const float2*)(g_ff + ((size_t)b * 255 + p) * F_ + n);
                    float2 cv  = *(const float2*)(g_c + ((size_t)b * NN + node) * F_ + n);
                    float2 o;
                    o.x = sigf(v.x + ffv.x) * cv.x;
                    o.y = sigf(v.y + ffv.y) * cv.y;
                    *(float2*)(g_fc + (size_t)m * F_ + n) = o;
                } else {
                    float2 fe = *(const float2*)(g_fe_iou + ((size_t)b * NN + p) * F3 + n);
                    v.x += fe.x; v.y += fe.y;
                    *(float2*)(g_iou + (size_t)m * F3 + n) = v;
                }
            }
        }
    }
}

// combined front GEMMs: fe_iou (6-wide col tiles of 256) then ff (2-wide)
__global__ void __launch_bounds__(256, 1)
front_k(const float* __restrict__ b_iou, const float* __restrict__ b_f) {
    extern __shared__ char smem[];
    int bx = blockIdx.x;
    if (bx < 768) {
        gemm_core<0>(smem, (bx / 6) * 128, (bx % 6) * 256, b_iou, 16352, 0, 0);
    } else {
        bx -= 768;
        gemm_core<1>(smem, (bx >> 1) * 128, (bx & 1) * 256, b_f, 8160, 0, 0);
    }
}

// fused per-level kernel: fc blocks first, iou blocks after
__global__ void __launch_bounds__(256, 1)
level_k(int s, int np, int yF, int Mf, int Mi) {
    extern __shared__ char smem[];
    int bx = blockIdx.x;
    if (bx < 2 * yF) {
        gemm_core<2>(smem, (bx >> 1) * 128, (bx & 1) * 256, nullptr, Mf, s, np);
    } else {
        bx -= 2 * yF;
        gemm_core<3>(smem, (bx / 6) * 128, (bx % 6) * 256, nullptr, Mi, s, np);
    }
}

// ======================= gates (pair-fused with hsum) =======================
__global__ void leafpair_k() {
    int idx = blockIdx.x * blockDim.x + threadIdx.x;  // 32*128*512
    int f = idx & 511, r = idx >> 9;   // r = b*128 + j
    int b = r >> 7, j = r & 127;
    float hs = 0.f;
    #pragma unroll
    for (int t = 0; t < 2; t++) {
        int node = 255 + 2 * j + t;
        size_t io = ((size_t)b * NN + node) * F3;
        float cn = sigf(g_fe_iou[io + f]) * fmaxf(g_fe_iou[io + 1024 + f], 0.f);
        float hn = sigf(g_fe_iou[io + 512 + f]) * tanhf(cn);
        size_t ho = ((size_t)b * NN + node) * F_ + f;
        g_c[ho] = cn;
        g_h[ho] = hn;
        g_ha[ho] = __float2half(hn);
        hs += hn;
    }
    g_hs[(size_t)r * F_ + f] = __float2half(hs);
}

__global__ void gatepair_k(int s, int np, int total) {
    int idx = blockIdx.x * blockDim.x + threadIdx.x;
    if (idx >= total) return;
    int f = idx & 511, r = idx >> 9;   // r = b*half + j
    int half = np >> 1;
    int b = r / half, j = r - b * half;
    float hs = 0.f;
    #pragma unroll
    for (int t = 0; t < 2; t++) {
        int pl = 2 * j + t;
        int rr = b * np + pl;
        int node = s + pl;
        size_t io = (size_t)rr * F3;
        float csum = g_fc[(size_t)(2 * rr) * F_ + f] + g_fc[(size_t)(2 * rr + 1) * F_ + f];
        float cn = sigf(g_iou[io + f]) * fmaxf(g_iou[io + 1024 + f], 0.f) + csum;
        float hn = sigf(g_iou[io + 512 + f]) * tanhf(cn);
        size_t ho = ((size_t)b * NN + node) * F_ + f;
        g_c[ho] = cn;
        g_h[ho] = hn;
        g_ha[ho] = __float2half(hn);
        hs += hn;
    }
    g_hs[(size_t)r * F_ + f] = __float2half(hs);
}

// ======================= readout (root gate fused into rscore) =======================
__global__ void rscore_k() {
    int gw = (blockIdx.x * blockDim.x + threadIdx.x) >> 5;
    int lane = threadIdx.x & 31;
    if (gw >= B_ * NN) return;
    int b = gw / NN;
    int i = gw - b * NN;
    float s = 0.f;
    if (i == 0) {
        // root gate: level 8 left g_iou rows r=b (np=1) and g_fc rows 2b, 2b+1
        size_t io = (size_t)b * F3;
        for (int f = lane; f < F_; f += 32) {
            float csum = g_fc[(size_t)(2 * b) * F_ + f] + g_fc[(size_t)(2 * b + 1) * F_ + f];
            float cn = sigf(g_iou[io + f]) * fmaxf(g_iou[io + 1024 + f], 0.f) + csum;
            float hn = sigf(g_iou[io + 512 + f]) * tanhf(cn);
            g_h[(size_t)b * NN * F_ + f] = hn;   // node 0 row, read by final_k
            s += hn * g_eforw[b * F_ + f];
        }
    } else {
        const float4* hp = (const float4*)(g_h + (size_t)gw * F_);
        const float4* ep = (const float4*)(g_eforw + b * F_);
        for (int t = lane; t < 128; t += 32) {
            float4 h = hp[t], e = ep[t];
            s += h.x * e.x + h.y * e.y + h.z * e.z + h.w * e.w;
        }
    }
    #pragma unroll
    for (int off = 16; off; off >>= 1) s += __shfl_xor_sync(0xffffffffu, s, off);
    if (!lane) g_r[b * 512 + i] = s;
}

__global__ void final_k(float* __restrict__ out) {
    __shared__ float red[128];
    __shared__ float pr[NN];
    int b = blockIdx.y, tid = threadIdx.x;
    float mx = -1e30f;
    for (int i = tid; i < NN; i += 128) mx = fmaxf(mx, g_r[b * 512 + i]);
    red[tid] = mx;
    __syncthreads();
    for (int o = 64; o; o >>= 1) {
        if (tid < o) red[tid] = fmaxf(red[tid], red[tid + o]);
        __syncthreads();
    }
    mx = red[0];
    __syncthreads();
    float sm = 0.f;
    for (int i = tid; i < NN; i += 128) {
        float e = expf(g_r[b * 512 + i] - mx);
        pr[i] = e;
        sm += e;
    }
    red[tid] = sm;
    __syncthreads();
    for (int o = 64; o; o >>= 1) {
        if (tid < o) red[tid] += red[tid + o];
        __syncthreads();
    }
    float inv = 1.f / red[0];
    __syncthreads();
    int f = blockIdx.x * 128 + tid;
    float acc = 0.f;
    for (int i = 0; i < NN; i++) acc += pr[i] * g_h[((size_t)b * NN + i) * F_ + f];
    out[b * F_ + f] = acc * inv;
}

// ======================= launcher =======================
extern "C" void kernel_launch(void* const* d_in, const int* in_sizes, int n_in,
                              void* d_out, int out_size) {
    const float* feat     = (const float*)d_in[0];
    const float* eh       = (const float*)d_in[5];
    const float* Wn       = (const float*)d_in[6];
    const float* Wf       = (const float*)d_in[7];
    const float* W_iou    = (const float*)d_in[8];
    const float* W_fe_iou = (const float*)d_in[9];
    const float* b_fe_iou = (const float*)d_in[10];
    const float* W_f      = (const float*)d_in[11];
    const float* W_fe_f   = (const float*)d_in[12];
    const float* b_fe_f   = (const float*)d_in[13];
    float* out = (float*)d_out;

    static bool attr_done = false;
    if (!attr_done) {
        cudaFuncSetAttribute(front_k, cudaFuncAttributeMaxDynamicSharedMemorySize, SMEM_TOT);
        cudaFuncSetAttribute(level_k, cudaFuncAttributeMaxDynamicSharedMemorySize, SMEM_TOT);
        attr_done = true;
    }

    prolog_k<<<8192 + 4096, 256>>>(W_fe_iou, W_fe_f, W_f, W_iou, eh, Wn, Wf);
    scores_k<<<2044, 256>>>(feat);
    feat2_k<<<dim3(8, B_, 4), 128>>>(feat);

    // fe_iou (M=16352,N=1536: 128x6 tiles) + ff (M=8160,N=512: 64x2 tiles)
    front_k<<<768 + 128, 256, SMEM_TOT>>>(b_fe_iou, b_fe_f);

    leafpair_k<<<(B_ * 128 * F_) / 256, 256>>>();

    for (int n = 1; n <= 8; n++) {
        int np = 1 << (8 - n);
        int s = np - 1;
        int Mf = B_ * 2 * np;
        int Mi = B_ * np;
        int yF = (Mf + 127) / 128;
        int yI = (Mi + 127) / 128;
        level_k<<<2 * yF + 6 * yI, 256, SMEM_TOT>>>(s, np, yF, Mf, Mi);
        if (np > 1) {
            int total = B_ * (np >> 1) * F_;
            gatepair_k<<<(total + 255) / 256, 256>>>(s, np, total);
        }
        // np == 1: root gate is fused into rscore_k below
    }

    rscore_k<<<2044, 256>>>();
    final_k<<<dim3(4, B_), 128>>>(out);
}

// round 16
// speedup vs baseline: 1.3997x; 1.3997x over previous
#include <cuda_runtime.h>
#include <cuda_fp16.h>
#include <math.h>
#include <cstdint>

#define B_ 32
#define NN 511
#define F_ 512
#define F3 1536

// ======================= scratch (static device globals) =======================
static __device__ __align__(16) float g_enode[B_ * F_];
static __device__ __align__(16) float g_eforw[B_ * F_];
static __device__ __align__(16) float g_scores[B_ * 512];
static __device__ __align__(16) float g_fe_iou[(size_t)B_ * NN * F3];
static __device__ __align__(16) float g_ff[(size_t)B_ * 255 * F_];
static __device__ __align__(16) float g_h[(size_t)B_ * NN * F_];
static __device__ __align__(16) float g_c[(size_t)B_ * NN * F_];
static __device__ __align__(16) float g_fc[(size_t)B_ * 256 * F_];
static __device__ __align__(16) float g_iou[(size_t)B_ * 128 * F3];
static __device__ __align__(16) float g_r[B_ * 512];
static __device__ int g_sync[8];
// fp16 activations (single precision-rounded copy)
static __device__ __align__(16) __half g_f2[(size_t)B_ * NN * F_];
static __device__ __align__(16) __half g_ha[(size_t)B_ * NN * F_];
static __device__ __align__(16) __half g_hs[(size_t)B_ * 128 * F_];
// fp16 hi/lo weights
static __device__ __align__(16) __half g_wfeiou_h[F3 * F_], g_wfeiou_l[F3 * F_];
static __device__ __align__(16) __half g_wfef_h[F_ * F_],  g_wfef_l[F_ * F_];
static __device__ __align__(16) __half g_wf_h[F_ * F_],    g_wf_l[F_ * F_];
static __device__ __align__(16) __half g_wiou_h[F3 * F_],  g_wiou_l[F3 * F_];

__device__ __forceinline__ float sigf(float x) { return 1.f / (1.f + expf(-x)); }
__device__ __forceinline__ void split_h(float x, __half& h, __half& l) {
    h = __float2half(x);
    l = __float2half(x - __half2float(h));
}

__device__ __forceinline__ uint32_t smem_u32(const void* p) {
    uint32_t a;
    asm("{ .reg .u64 t; cvta.to.shared.u64 t, %1; cvt.u32.u64 %0, t; }" : "=r"(a) : "l"(p));
    return a;
}

#define CP16(dst, src) \
    asm volatile("cp.async.cg.shared.global [%0], [%1], 16;" :: "r"(dst), "l"(src) : "memory")
#define CP_COMMIT() asm volatile("cp.async.commit_group;" ::: "memory")
template <int N>
__device__ __forceinline__ void cp_wait() {
    asm volatile("cp.async.wait_group %0;" :: "n"(N) : "memory");
}

__device__ __forceinline__ void mma16816(float* c, const uint32_t* a, const uint32_t* b) {
    asm volatile(
        "mma.sync.aligned.m16n8k16.row.col.f32.f16.f16.f32 "
        "{%0,%1,%2,%3}, {%4,%5,%6,%7}, {%8,%9}, {%0,%1,%2,%3};"
        : "+f"(c[0]), "+f"(c[1]), "+f"(c[2]), "+f"(c[3])
        : "r"(a[0]), "r"(a[1]), "r"(a[2]), "r"(a[3]), "r"(b[0]), "r"(b[1]));
}

__device__ __forceinline__ void ldsm4(uint32_t& r0, uint32_t& r1, uint32_t& r2, uint32_t& r3,
                                      uint32_t addr) {
    asm volatile("ldmatrix.sync.aligned.m8n8.x4.shared.b16 {%0,%1,%2,%3}, [%4];"
                 : "=r"(r0), "=r"(r1), "=r"(r2), "=r"(r3) : "r"(addr));
}

// software grid barrier (all blocks resident; counters zeroed by prolog_k each launch)
__device__ __forceinline__ void gsync(int p) {
    __syncthreads();
    if (threadIdx.x == 0) {
        __threadfence();
        atomicAdd(&g_sync[p], 1);
        while (*(volatile int*)&g_sync[p] < (int)gridDim.x) { }
        __threadfence();
    }
    __syncthreads();
}

// ======================= prologue (weight conversion + enode/eforw fused) =======================
__global__ void prolog_k(const float* __restrict__ s0, const float* __restrict__ s1,
                         const float* __restrict__ s2, const float* __restrict__ s3,
                         const float* __restrict__ eh, const float* __restrict__ Wn,
                         const float* __restrict__ Wf) {
    int bx = blockIdx.x;
    if (bx == 0 && threadIdx.x < 8) g_sync[threadIdx.x] = 0;
    if (bx < 8192) {
        int i = bx * 256 + threadIdx.x;  // total 2097152
        if (i < 786432) {
            split_h(s0[i], g_wfeiou_h[i], g_wfeiou_l[i]);
        } else if (i < 1048576) {
            int j = i - 786432;
            split_h(s1[j], g_wfef_h[j], g_wfef_l[j]);
        } else if (i < 1310720) {
            int j = i - 1048576;
            split_h(s2[j], g_wf_h[j], g_wf_l[j]);
        } else {
            int j = i - 1310720;
            split_h(s3[j], g_wiou_h[j], g_wiou_l[j]);
        }
    } else {
        bx -= 8192;                       // 4096 blocks: x(64) | b(32) | z(2)
        int x = bx & 63, b = (bx >> 6) & 31, z = bx >> 11;
        int warp = threadIdx.x >> 5, lane = threadIdx.x & 31;
        int j = x * 8 + warp;
        const float* W = z ? Wf : Wn;
        float* o = z ? g_eforw : g_enode;
        const float4* wr = (const float4*)(W + (size_t)j * 1024);
        const float4* er = (const float4*)(eh + (size_t)b * 1024);
        float s = 0.f;
        for (int t = lane; t < 256; t += 32) {
            float4 w = wr[t], e = er[t];
            s += w.x * e.x + w.y * e.y + w.z * e.z + w.w * e.w;
        }
        #pragma unroll
        for (int off = 16; off; off >>= 1) s += __shfl_xor_sync(0xffffffffu, s, off);
        if (!lane) o[b * F_ + j] = s;
    }
}

__global__ void scores_k(const float* __restrict__ feat) {
    int gw = (blockIdx.x * blockDim.x + threadIdx.x) >> 5;
    int lane = threadIdx.x & 31;
    if (gw >= B_ * NN) return;
    int b = gw / NN;
    const float4* fr = (const float4*)(feat + (size_t)gw * F_);
    const float4* er = (const float4*)(g_enode + b * F_);
    float s = 0.f;
    for (int t = lane; t < 128; t += 32) {
        float4 f = fr[t], e = er[t];
        s += f.x * e.x + f.y * e.y + f.z * e.z + f.w * e.w;
    }
    #pragma unroll
    for (int off = 16; off; off >>= 1) s += __shfl_xor_sync(0xffffffffu, s, off);
    if (!lane) g_scores[b * 512 + (gw - b * NN)] = s;
}

// ---------------- streaming feat2: rolling 4-row window ----------------
__global__ void __launch_bounds__(128)
feat2_k(const float* __restrict__ feat) {
    __shared__ float pr[64][4];
    const int ic = blockIdx.x, b = blockIdx.y, fch = blockIdx.z;
    const int tid = threadIdx.x;
    const int start = ic * 64;

    if (tid < 64) {
        int i = start + tid;
        if (i < NN) {
            int cnt = min(i + 3, NN - 1) - i + 1;
            float sc[4], mx = -1e30f;
            #pragma unroll
            for (int k = 0; k < 4; k++) {
                sc[k] = (k < cnt) ? g_scores[b * 512 + i + k] : -1e30f;
                mx = fmaxf(mx, sc[k]);
            }
            float sum = 0.f;
            #pragma unroll
            for (int k = 0; k < 4; k++) {
                sc[k] = (k < cnt) ? expf(sc[k] - mx) : 0.f;
                sum += sc[k];
            }
            float inv = 1.f / sum;
            #pragma unroll
            for (int k = 0; k < 4; k++) pr[tid][k] = sc[k] * inv;
        }
    }
    __syncthreads();

    const int f = fch * 128 + tid;
    const float* fb = feat + ((size_t)b * NN) * F_ + f;
    float r0 = fb[(size_t)min(start, NN - 1) * F_];
    float r1 = fb[(size_t)min(start + 1, NN - 1) * F_];
    float r2 = fb[(size_t)min(start + 2, NN - 1) * F_];
    size_t obase = ((size_t)b * NN + start) * F_ + f;
    const int nout = min(64, NN - start);
    for (int j = 0; j < nout; j++) {
        int i = start + j;
        float r3 = fb[(size_t)min(i + 3, NN - 1) * F_];
        float a = pr[j][0] * r0 + pr[j][1] * r1 + pr[j][2] * r2 + pr[j][3] * r3;
        g_f2[obase] = __float2half(a);
        obase += F_;
        r0 = r1; r1 = r2; r2 = r3;
    }
}

// ======================= HMMA GEMM core (fp16, fp32 acc, k-chunk 64) =======================
// Block tile 128x128x64, 8 warps (2M x 4N), warp tile 64x32, ldmatrix fragments.
// 2-stage cp.async pipeline (55KB/stage), 2 CTAs/SM, 8 chunks.  (round-11 validated config)
// MODE 0: fe_iou = feat2 @ W_fe_iou^T + bias          (2-pass W hi/lo)
// MODE 1: ff     = feat2[parents] @ W_fe_f^T + bias   (1-pass, sigmoid-damped)
// MODE 2: fc     = sigmoid(h[child] @ W_f^T + ff[parent]) * c[child]  (1-pass)
// MODE 3: iou    = hsum @ W_iou^T + fe_iou[parent]    (2-pass W hi/lo)
#define ROWP 144
#define TILE_B (128 * ROWP)          // 18432
#define STAGE_B (3 * TILE_B)         // 55296
#define SMEM_TOT (2 * STAGE_B)       // 110592

template <int MODE>
__device__ __forceinline__ void gemm_core(char* smem, int bm, int bn,
                                          const float* __restrict__ bias,
                                          int M, int s, int np) {
    constexpr bool TP = (MODE == 0 || MODE == 3);   // two-pass weights
    const uint32_t sb = smem_u32(smem);
    const int tid = threadIdx.x;
    const int warp = tid >> 5, lane = tid & 31;
    const int wm = warp >> 2, wn = warp & 3;
    const int qrow = lane >> 2, qcol = (lane & 3) * 2;

    const __half *Aa, *Wh, *Wl;
    if (MODE == 0) { Aa = g_f2; Wh = g_wfeiou_h; Wl = g_wfeiou_l; }
    else if (MODE == 1) { Aa = g_f2; Wh = g_wfef_h; Wl = g_wfef_l; }
    else if (MODE == 2) { Aa = g_ha; Wh = g_wf_h; Wl = g_wf_l; }
    else { Aa = g_hs; Wh = g_wiou_h; Wl = g_wiou_l; }

    // --- cp.async geometry: rows rowb+32j (j=0..3), one 16B group of the 128B row ---
    const int quad = tid & 7;        // 16B group (8 per row)
    const int rowb = tid >> 3;       // 0..31
    int ar[4], wr[4];
    uint32_t dd[4];
    #pragma unroll
    for (int j = 0; j < 4; j++) {
        int r = rowb + j * 32;
        int rA = min(bm + r, M - 1);
        int arow;
        if (MODE == 0 || MODE == 3) arow = rA;
        else if (MODE == 1) { int b0 = rA / 255; arow = b0 * NN + (rA - b0 * 255); }
        else { int two = 2 * np; int b0 = rA / two; arow = b0 * NN + 2 * s + 1 + (rA - b0 * two); }
        ar[j] = arow * F_ + quad * 8;
        wr[j] = (bn + r) * F_ + quad * 8;
        dd[j] = (uint32_t)(r * ROWP + quad * 16);
    }

    // --- ldmatrix lane offsets ---
    const uint32_t a_l = (uint32_t)((wm * 64 + (lane & 15)) * ROWP + (lane >> 4) * 16);
    const uint32_t b_l = (uint32_t)((wn * 32 + ((lane >> 4) & 1) * 8 + (lane & 7)) * ROWP +
                                    ((lane >> 3) & 1) * 16);

#define LOAD_CHUNK(cidx, stgi) do {                                        \
    int k0 = (cidx) * 64;                                                  \
    uint32_t s0a = sb + (stgi) * STAGE_B;                                  \
    CP16(s0a + dd[0], Aa + ar[0] + k0);                                    \
    CP16(s0a + dd[1], Aa + ar[1] + k0);                                    \
    CP16(s0a + dd[2], Aa + ar[2] + k0);                                    \
    CP16(s0a + dd[3], Aa + ar[3] + k0);                                    \
    CP16(s0a + TILE_B + dd[0], Wh + wr[0] + k0);                           \
    CP16(s0a + TILE_B + dd[1], Wh + wr[1] + k0);                           \
    CP16(s0a + TILE_B + dd[2], Wh + wr[2] + k0);                           \
    CP16(s0a + TILE_B + dd[3], Wh + wr[3] + k0);                           \
    if (TP) {                                                              \
        CP16(s0a + 2 * TILE_B + dd[0], Wl + wr[0] + k0);                   \
        CP16(s0a + 2 * TILE_B + dd[1], Wl + wr[1] + k0);                   \
        CP16(s0a + 2 * TILE_B + dd[2], Wl + wr[2] + k0);                   \
        CP16(s0a + 2 * TILE_B + dd[3], Wl + wr[3] + k0);                   \
    }                                                                      \
    CP_COMMIT();                                                          \
} while (0)

    float acc[4][4][4] = {};

    LOAD_CHUNK(0, 0);

    for (int c = 0; c < 8; c++) {
        if (c) __syncthreads();          // prior compute on the stage LOAD will overwrite is done
        if (c < 7) LOAD_CHUNK(c + 1, (c + 1) & 1);
        if (c < 7) cp_wait<1>(); else cp_wait<0>();
        __syncthreads();                 // chunk-c data visible to all threads

        const uint32_t stg = sb + (c & 1) * STAGE_B;
        #pragma unroll
        for (int kk = 0; kk < 4; kk++) {
            uint32_t ah[4][4], bh[2][4], bl[2][4];
            #pragma unroll
            for (int mf = 0; mf < 4; mf++) {
                ldsm4(ah[mf][0], ah[mf][1], ah[mf][2], ah[mf][3],
                      stg + a_l + mf * 2304 + kk * 32);
            }
            #pragma unroll
            for (int p = 0; p < 2; p++) {
                uint32_t baddr = stg + TILE_B + b_l + p * 2304 + kk * 32;
                ldsm4(bh[p][0], bh[p][1], bh[p][2], bh[p][3], baddr);
                if (TP) ldsm4(bl[p][0], bl[p][1], bl[p][2], bl[p][3], baddr + TILE_B);
            }
            #pragma unroll
            for (int mf = 0; mf < 4; mf++)
                #pragma unroll
                for (int p = 0; p < 2; p++)
                    #pragma unroll
                    for (int q = 0; q < 2; q++) {
                        int nf = p * 2 + q;
                        mma16816(acc[mf][nf], ah[mf], &bh[p][2 * q]);
                        if (TP) mma16816(acc[mf][nf], ah[mf], &bl[p][2 * q]);
                    }
        }
    }
#undef LOAD_CHUNK

    // --- epilogue ---
    #pragma unroll
    for (int mf = 0; mf < 4; mf++) {
        #pragma unroll
        for (int half = 0; half < 2; half++) {
            int m = bm + wm * 64 + mf * 16 + qrow + half * 8;
            if (m >= M) continue;
            int b = 0, node = 0, p = 0;
            if (MODE == 2) {
                int two = 2 * np;
                b = m / two;
                int cl = m - b * two;
                node = 2 * s + 1 + cl;
                p = s + (cl >> 1);
            } else if (MODE == 3) {
                b = m / np;
                p = s + (m - b * np);
            }
            #pragma unroll
            for (int nf = 0; nf < 4; nf++) {
                int n = bn + wn * 32 + nf * 8 + qcol;
                float2 v = make_float2(acc[mf][nf][half * 2], acc[mf][nf][half * 2 + 1]);
                if (MODE == 0) {
                    float2 bi = *(const float2*)(bias + n);
                    v.x += bi.x; v.y += bi.y;
                    *(float2*)(g_fe_iou + (size_t)m * F3 + n) = v;
                } else if (MODE == 1) {
                    float2 bi = *(const float2*)(bias + n);
                    v.x += bi.x; v.y += bi.y;
                    *(float2*)(g_ff + (size_t)m * F_ + n) = v;
                } else if (MODE == 2) {
                    // __ldcg: same-launch cross-block producers inside tail_k (L2-coherent path)
                    float2 ffv = __ldcg((const float2*)(g_ff + ((size_t)b * 255 + p) * F_ + n));
                    float2 cv  = __ldcg((const float2*)(g_c + ((size_t)b * NN + node) * F_ + n));
                    float2 o;
                    o.x = sigf(v.x + ffv.x) * cv.x;
                    o.y = sigf(v.y + ffv.y) * cv.y;
                    *(float2*)(g_fc + (size_t)m * F_ + n) = o;
                } else {
                    float2 fe = *(const float2*)(g_fe_iou + ((size_t)b * NN + p) * F3 + n);
                    v.x += fe.x; v.y += fe.y;
                    *(float2*)(g_iou + (size_t)m * F3 + n) = v;
                }
            }
        }
    }
}

// combined front GEMMs: fe_iou (12-wide tiles) then ff (4-wide tiles)
__global__ void __launch_bounds__(256, 2)
front_k(const float* __restrict__ b_iou, const float* __restrict__ b_f) {
    extern __shared__ char smem[];
    int bx = blockIdx.x;
    if (bx < 1536) {
        gemm_core<0>(smem, (bx / 12) * 128, (bx % 12) * 128, b_iou, 16352, 0, 0);
    } else {
        bx -= 1536;
        gemm_core<1>(smem, (bx >> 2) * 128, (bx & 3) * 128, b_f, 8160, 0, 0);
    }
}

// fused per-level kernel (levels 1..3): fc blocks first, iou blocks after
__global__ void __launch_bounds__(256, 2)
level_k(int s, int np, int yF, int Mf, int Mi) {
    extern __shared__ char smem[];
    int bx = blockIdx.x;
    if (bx < 4 * yF) {
        gemm_core<2>(smem, (bx >> 2) * 128, (bx & 3) * 128, nullptr, Mf, s, np);
    } else {
        bx -= 4 * yF;
        gemm_core<3>(smem, (bx / 12) * 128, (bx % 12) * 128, nullptr, Mi, s, np);
    }
}

// ======================= gate body (pair-fused with hsum; L2 loads) =======================
__device__ __forceinline__ void gate_body(int idx, int s, int np) {
    int f = idx & 511, r = idx >> 9;   // r = b*half + j
    int half = np >> 1;
    int b = r / half, j = r - b * half;
    float hs = 0.f;
    #pragma unroll
    for (int t = 0; t < 2; t++) {
        int pl = 2 * j + t;
        int rr = b * np + pl;
        int node = s + pl;
        size_t io = (size_t)rr * F3;
        float csum = __ldcg(g_fc + (size_t)(2 * rr) * F_ + f) +
                     __ldcg(g_fc + (size_t)(2 * rr + 1) * F_ + f);
        float cn = sigf(__ldcg(g_iou + io + f)) * fmaxf(__ldcg(g_iou + io + 1024 + f), 0.f) + csum;
        float hn = sigf(__ldcg(g_iou + io + 512 + f)) * tanhf(cn);
        size_t ho = ((size_t)b * NN + node) * F_ + f;
        g_c[ho] = cn;
        g_h[ho] = hn;
        g_ha[ho] = __float2half(hn);
        hs += hn;
    }
    g_hs[(size_t)r * F_ + f] = __float2half(hs);
}

__global__ void gatepair_k(int s, int np, int total) {
    int idx = blockIdx.x * blockDim.x + threadIdx.x;
    if (idx >= total) return;
    gate_body(idx, s, np);
}

__global__ void leafpair_k() {
    int idx = blockIdx.x * blockDim.x + threadIdx.x;  // 32*128*512
    int f = idx & 511, r = idx >> 9;   // r = b*128 + j
    int b = r >> 7, j = r & 127;
    float hs = 0.f;
    #pragma unroll
    for (int t = 0; t < 2; t++) {
        int node = 255 + 2 * j + t;
        size_t io = ((size_t)b * NN + node) * F3;
        float cn = sigf(g_fe_iou[io + f]) * fmaxf(g_fe_iou[io + 1024 + f], 0.f);
        float hn = sigf(g_fe_iou[io + 512 + f]) * tanhf(cn);
        size_t ho = ((size_t)b * NN + node) * F_ + f;
        g_c[ho] = cn;
        g_h[ho] = hn;
        g_ha[ho] = __float2half(hn);
        hs += hn;
    }
    g_hs[(size_t)r * F_ + f] = __float2half(hs);
}

// ======================= persistent tail: levels 4..8 + gates, one launch =======================
// 80 blocks, all resident (2 CTAs/SM capacity = 296) -> spin barrier is deadlock-free.
__global__ void __launch_bounds__(256, 2)
tail_k() {
    extern __shared__ char smem[];
    int phase = 0;
    #pragma unroll 1
    for (int n = 4; n <= 8; n++) {
        int np = 1 << (8 - n);
        int s = np - 1;
        int Mf = B_ * 2 * np;
        int Mi = B_ * np;
        int yF = (Mf + 127) / 128;
        int yI = (Mi + 127) / 128;
        int nblk = 4 * yF + 12 * yI;
        int bx = blockIdx.x;
        if (bx < nblk) {
            if (bx < 4 * yF) {
                gemm_core<2>(smem, (bx >> 2) * 128, (bx & 3) * 128, nullptr, Mf, s, np);
            } else {
                bx -= 4 * yF;
                gemm_core<3>(smem, (bx / 12) * 128, (bx % 12) * 128, nullptr, Mi, s, np);
            }
        }
        if (n == 8) break;               // root gate is fused into rscore_k
        gsync(phase++);
        int total = B_ * (np >> 1) * F_;
        for (int idx = blockIdx.x * 256 + threadIdx.x; idx < total; idx += gridDim.x * 256)
            gate_body(idx, s, np);
        gsync(phase++);
    }
}

// ======================= readout (root gate fused into rscore) =======================
__global__ void rscore_k() {
    int gw = (blockIdx.x * blockDim.x + threadIdx.x) >> 5;
    int lane = threadIdx.x & 31;
    if (gw >= B_ * NN) return;
    int b = gw / NN;
    int i = gw - b * NN;
    float s = 0.f;
    if (i == 0) {
        // root gate: level 8 left g_iou rows r=b (np=1) and g_fc rows 2b, 2b+1
        size_t io = (size_t)b * F3;
        for (int f = lane; f < F_; f += 32) {
            float csum = g_fc[(size_t)(2 * b) * F_ + f] + g_fc[(size_t)(2 * b + 1) * F_ + f];
            float cn = sigf(g_iou[io + f]) * fmaxf(g_iou[io + 1024 + f], 0.f) + csum;
            float hn = sigf(g_iou[io + 512 + f]) * tanhf(cn);
            g_h[(size_t)b * NN * F_ + f] = hn;   // node 0 row, read by final_k
            s += hn * g_eforw[b * F_ + f];
        }
    } else {
        const float4* hp = (const float4*)(g_h + (size_t)gw * F_);
        const float4* ep = (const float4*)(g_eforw + b * F_);
        for (int t = lane; t < 128; t += 32) {
            float4 h = hp[t], e = ep[t];
            s += h.x * e.x + h.y * e.y + h.z * e.z + h.w * e.w;
        }
    }
    #pragma unroll
    for (int off = 16; off; off >>= 1) s += __shfl_xor_sync(0xffffffffu, s, off);
    if (!lane) g_r[b * 512 + i] = s;
}

__global__ void final_k(float* __restrict__ out) {
    __shared__ float red[128];
    __shared__ float pr[NN];
    int b = blockIdx.y, tid = threadIdx.x;
    float mx = -1e30f;
    for (int i = tid; i < NN; i += 128) mx = fmaxf(mx, g_r[b * 512 + i]);
    red[tid] = mx;
    __syncthreads();
    for (int o = 64; o; o >>= 1) {
        if (tid < o) red[tid] = fmaxf(red[tid], red[tid + o]);
        __syncthreads();
    }
    mx = red[0];
    __syncthreads();
    float sm = 0.f;
    for (int i = tid; i < NN; i += 128) {
        float e = expf(g_r[b * 512 + i] - mx);
        pr[i] = e;
        sm += e;
    }
    red[tid] = sm;
    __syncthreads();
    for (int o = 64; o; o >>= 1) {
        if (tid < o) red[tid] += red[tid + o];
        __syncthreads();
    }
    float inv = 1.f / red[0];
    __syncthreads();
    int f = blockIdx.x * 128 + tid;
    float acc = 0.f;
    for (int i = 0; i < NN; i++) acc += pr[i] * g_h[((size_t)b * NN + i) * F_ + f];
    out[b * F_ + f] = acc * inv;
}

// ======================= launcher =======================
extern "C" void kernel_launch(void* const* d_in, const int* in_sizes, int n_in,
                              void* d_out, int out_size) {
    const float* feat     = (const float*)d_in[0];
    const float* eh       = (const float*)d_in[5];
    const float* Wn       = (const float*)d_in[6];
    const float* Wf       = (const float*)d_in[7];
    const float* W_iou    = (const float*)d_in[8];
    const float* W_fe_iou = (const float*)d_in[9];
    const float* b_fe_iou = (const float*)d_in[10];
    const float* W_f      = (const float*)d_in[11];
    const float* W_fe_f   = (const float*)d_in[12];
    const float* b_fe_f   = (const float*)d_in[13];
    float* out = (float*)d_out;

    static bool attr_done = false;
    if (!attr_done) {
        cudaFuncSetAttribute(front_k, cudaFuncAttributeMaxDynamicSharedMemorySize, SMEM_TOT);
        cudaFuncSetAttribute(level_k, cudaFuncAttributeMaxDynamicSharedMemorySize, SMEM_TOT);
        cudaFuncSetAttribute(tail_k, cudaFuncAttributeMaxDynamicSharedMemorySize, SMEM_TOT);
        attr_done = true;
    }

    prolog_k<<<8192 + 4096, 256>>>(W_fe_iou, W_fe_f, W_f, W_iou, eh, Wn, Wf);
    scores_k<<<2044, 256>>>(feat);
    feat2_k<<<dim3(8, B_, 4), 128>>>(feat);

    // fe_iou (M=16352,N=1536) + ff (M=8160,N=512) in one launch
    front_k<<<1536 + 256, 256, SMEM_TOT>>>(b_fe_iou, b_fe_f);

    leafpair_k<<<(B_ * 128 * F_) / 256, 256>>>();

    // big levels 1..3: separate launches (grids 640/320/160 — fill the chip)
    for (int n = 1; n <= 3; n++) {
        int np = 1 << (8 - n);
        int s = np - 1;
        int Mf = B_ * 2 * np;
        int Mi = B_ * np;
        int yF = (Mf + 127) / 128;
        int yI = (Mi + 127) / 128;
        level_k<<<4 * yF + 12 * yI, 256, SMEM_TOT>>>(s, np, yF, Mf, Mi);
        int total = B_ * (np >> 1) * F_;
        gatepair_k<<<(total + 255) / 256, 256>>>(s, np, total);
    }

    // small levels 4..8 + gates: one persistent launch with software grid syncs
    tail_k<<<80, 256, SMEM_TOT>>>();

    rscore_k<<<2044, 256>>>();
    final_k<<<dim3(4, B_), 128>>>(out);
}

// round 17
// speedup vs baseline: 1.5786x; 1.1279x over previous
#include <cuda_runtime.h>
#include <cuda_fp16.h>
#include <math.h>
#include <cstdint>

#define B_ 32
#define NN 511
#define F_ 512
#define F3 1536

// ======================= scratch (static device globals) =======================
static __device__ __align__(16) float g_enode[B_ * F_];
static __device__ __align__(16) float g_eforw[B_ * F_];
static __device__ __align__(16) float g_scores[B_ * 512];
static __device__ __align__(16) float g_fe_iou[(size_t)B_ * NN * F3];
static __device__ __align__(16) float g_ff[(size_t)B_ * 255 * F_];
static __device__ __align__(16) float g_h[(size_t)B_ * NN * F_];
static __device__ __align__(16) float g_c[(size_t)B_ * NN * F_];
static __device__ __align__(16) float g_fc[(size_t)B_ * 256 * F_];
static __device__ __align__(16) float g_iou[(size_t)B_ * 128 * F3];
static __device__ __align__(16) float g_r[B_ * 512];
// fp16 activations (single precision-rounded copy)
static __device__ __align__(16) __half g_f2[(size_t)B_ * NN * F_];
static __device__ __align__(16) __half g_ha[(size_t)B_ * NN * F_];
static __device__ __align__(16) __half g_hs[(size_t)B_ * 128 * F_];
// fp16 weights (wiou keeps hi/lo two-pass; others single fp16)
static __device__ __align__(16) __half g_wfeiou_h[F3 * F_];
static __device__ __align__(16) __half g_wfef_h[F_ * F_];
static __device__ __align__(16) __half g_wf_h[F_ * F_];
static __device__ __align__(16) __half g_wiou_h[F3 * F_], g_wiou_l[F3 * F_];

__device__ __forceinline__ float sigf(float x) { return 1.f / (1.f + expf(-x)); }
__device__ __forceinline__ void split_h(float x, __half& h, __half& l) {
    h = __float2half(x);
    l = __float2half(x - __half2float(h));
}

__device__ __forceinline__ uint32_t smem_u32(const void* p) {
    uint32_t a;
    asm("{ .reg .u64 t; cvta.to.shared.u64 t, %1; cvt.u32.u64 %0, t; }" : "=r"(a) : "l"(p));
    return a;
}

#define CP16(dst, src) \
    asm volatile("cp.async.cg.shared.global [%0], [%1], 16;" :: "r"(dst), "l"(src) : "memory")
#define CP_COMMIT() asm volatile("cp.async.commit_group;" ::: "memory")
template <int N>
__device__ __forceinline__ void cp_wait() {
    asm volatile("cp.async.wait_group %0;" :: "n"(N) : "memory");
}

__device__ __forceinline__ void mma16816(float* c, const uint32_t* a, const uint32_t* b) {
    asm volatile(
        "mma.sync.aligned.m16n8k16.row.col.f32.f16.f16.f32 "
        "{%0,%1,%2,%3}, {%4,%5,%6,%7}, {%8,%9}, {%0,%1,%2,%3};"
        : "+f"(c[0]), "+f"(c[1]), "+f"(c[2]), "+f"(c[3])
        : "r"(a[0]), "r"(a[1]), "r"(a[2]), "r"(a[3]), "r"(b[0]), "r"(b[1]));
}

__device__ __forceinline__ void ldsm4(uint32_t& r0, uint32_t& r1, uint32_t& r2, uint32_t& r3,
                                      uint32_t addr) {
    asm volatile("ldmatrix.sync.aligned.m8n8.x4.shared.b16 {%0,%1,%2,%3}, [%4];"
                 : "=r"(r0), "=r"(r1), "=r"(r2), "=r"(r3) : "r"(addr));
}

// ======================= prologue (weight conversion + enode/eforw fused) =======================
__global__ void prolog_k(const float* __restrict__ s0, const float* __restrict__ s1,
                         const float* __restrict__ s2, const float* __restrict__ s3,
                         const float* __restrict__ eh, const float* __restrict__ Wn,
                         const float* __restrict__ Wf) {
    int bx = blockIdx.x;
    if (bx < 8192) {
        int i = bx * 256 + threadIdx.x;  // total 2097152
        if (i < 786432) {
            g_wfeiou_h[i] = __float2half(s0[i]);
        } else if (i < 1048576) {
            int j = i - 786432;
            g_wfef_h[j] = __float2half(s1[j]);
        } else if (i < 1310720) {
            int j = i - 1048576;
            g_wf_h[j] = __float2half(s2[j]);
        } else {
            int j = i - 1310720;
            split_h(s3[j], g_wiou_h[j], g_wiou_l[j]);
        }
    } else {
        bx -= 8192;                       // 4096 blocks: x(64) | b(32) | z(2)
        int x = bx & 63, b = (bx >> 6) & 31, z = bx >> 11;
        int warp = threadIdx.x >> 5, lane = threadIdx.x & 31;
        int j = x * 8 + warp;
        const float* W = z ? Wf : Wn;
        float* o = z ? g_eforw : g_enode;
        const float4* wr = (const float4*)(W + (size_t)j * 1024);
        const float4* er = (const float4*)(eh + (size_t)b * 1024);
        float s = 0.f;
        for (int t = lane; t < 256; t += 32) {
            float4 w = wr[t], e = er[t];
            s += w.x * e.x + w.y * e.y + w.z * e.z + w.w * e.w;
        }
        #pragma unroll
        for (int off = 16; off; off >>= 1) s += __shfl_xor_sync(0xffffffffu, s, off);
        if (!lane) o[b * F_ + j] = s;
    }
}

__global__ void scores_k(const float* __restrict__ feat) {
    int gw = (blockIdx.x * blockDim.x + threadIdx.x) >> 5;
    int lane = threadIdx.x & 31;
    if (gw >= B_ * NN) return;
    int b = gw / NN;
    const float4* fr = (const float4*)(feat + (size_t)gw * F_);
    const float4* er = (const float4*)(g_enode + b * F_);
    float s = 0.f;
    for (int t = lane; t < 128; t += 32) {
        float4 f = fr[t], e = er[t];
        s += f.x * e.x + f.y * e.y + f.z * e.z + f.w * e.w;
    }
    #pragma unroll
    for (int off = 16; off; off >>= 1) s += __shfl_xor_sync(0xffffffffu, s, off);
    if (!lane) g_scores[b * 512 + (gw - b * NN)] = s;
}

// ---------------- streaming feat2: rolling 4-row window ----------------
__global__ void __launch_bounds__(128)
feat2_k(const float* __restrict__ feat) {
    __shared__ float pr[64][4];
    const int ic = blockIdx.x, b = blockIdx.y, fch = blockIdx.z;
    const int tid = threadIdx.x;
    const int start = ic * 64;

    if (tid < 64) {
        int i = start + tid;
        if (i < NN) {
            int cnt = min(i + 3, NN - 1) - i + 1;
            float sc[4], mx = -1e30f;
            #pragma unroll
            for (int k = 0; k < 4; k++) {
                sc[k] = (k < cnt) ? g_scores[b * 512 + i + k] : -1e30f;
                mx = fmaxf(mx, sc[k]);
            }
            float sum = 0.f;
            #pragma unroll
            for (int k = 0; k < 4; k++) {
                sc[k] = (k < cnt) ? expf(sc[k] - mx) : 0.f;
                sum += sc[k];
            }
            float inv = 1.f / sum;
            #pragma unroll
            for (int k = 0; k < 4; k++) pr[tid][k] = sc[k] * inv;
        }
    }
    __syncthreads();

    const int f = fch * 128 + tid;
    const float* fb = feat + ((size_t)b * NN) * F_ + f;
    float r0 = fb[(size_t)min(start, NN - 1) * F_];
    float r1 = fb[(size_t)min(start + 1, NN - 1) * F_];
    float r2 = fb[(size_t)min(start + 2, NN - 1) * F_];
    size_t obase = ((size_t)b * NN + start) * F_ + f;
    const int nout = min(64, NN - start);
    for (int j = 0; j < nout; j++) {
        int i = start + j;
        float r3 = fb[(size_t)min(i + 3, NN - 1) * F_];
        float a = pr[j][0] * r0 + pr[j][1] * r1 + pr[j][2] * r2 + pr[j][3] * r3;
        g_f2[obase] = __float2half(a);
        obase += F_;
        r0 = r1; r1 = r2; r2 = r3;
    }
}

// ======================= HMMA GEMM core (fp16, fp32 acc, k-chunk 64) =======================
// Block tile 128x128x64, 8 warps (2M x 4N), warp tile 64x32, ldmatrix fragments.
// 2-stage cp.async pipeline (55KB/stage), 2 CTAs/SM, 8 chunks.  (round-11 validated config)
// MODE 0: fe_iou = feat2 @ W_fe_iou^T + bias          (1-pass fp16)
// MODE 1: ff     = feat2[parents] @ W_fe_f^T + bias   (1-pass, sigmoid-damped)
// MODE 2: fc     = sigmoid(h[child] @ W_f^T + ff[parent]) * c[child]  (1-pass)
// MODE 3: iou    = hsum @ W_iou^T + fe_iou[parent]    (2-pass W hi/lo)
#define ROWP 144
#define TILE_B (128 * ROWP)          // 18432
#define STAGE_B (3 * TILE_B)         // 55296
#define SMEM_TOT (2 * STAGE_B)       // 110592

template <int MODE>
__device__ __forceinline__ void gemm_core(char* smem, int bm, int bn,
                                          const float* __restrict__ bias,
                                          int M, int s, int np) {
    constexpr bool TP = (MODE == 3);                // two-pass weights (iou chain only)
    const uint32_t sb = smem_u32(smem);
    const int tid = threadIdx.x;
    const int warp = tid >> 5, lane = tid & 31;
    const int wm = warp >> 2, wn = warp & 3;
    const int qrow = lane >> 2, qcol = (lane & 3) * 2;

    const __half *Aa, *Wh, *Wl;
    if (MODE == 0) { Aa = g_f2; Wh = g_wfeiou_h; Wl = g_wfeiou_h; }
    else if (MODE == 1) { Aa = g_f2; Wh = g_wfef_h; Wl = g_wfef_h; }
    else if (MODE == 2) { Aa = g_ha; Wh = g_wf_h; Wl = g_wf_h; }
    else { Aa = g_hs; Wh = g_wiou_h; Wl = g_wiou_l; }

    // --- cp.async geometry: rows rowb+32j (j=0..3), one 16B group of the 128B row ---
    const int quad = tid & 7;        // 16B group (8 per row)
    const int rowb = tid >> 3;       // 0..31
    int ar[4], wr[4];
    uint32_t dd[4];
    #pragma unroll
    for (int j = 0; j < 4; j++) {
        int r = rowb + j * 32;
        int rA = min(bm + r, M - 1);
        int arow;
        if (MODE == 0 || MODE == 3) arow = rA;
        else if (MODE == 1) { int b0 = rA / 255; arow = b0 * NN + (rA - b0 * 255); }
        else { int two = 2 * np; int b0 = rA / two; arow = b0 * NN + 2 * s + 1 + (rA - b0 * two); }
        ar[j] = arow * F_ + quad * 8;
        wr[j] = (bn + r) * F_ + quad * 8;
        dd[j] = (uint32_t)(r * ROWP + quad * 16);
    }

    // --- ldmatrix lane offsets ---
    const uint32_t a_l = (uint32_t)((wm * 64 + (lane & 15)) * ROWP + (lane >> 4) * 16);
    const uint32_t b_l = (uint32_t)((wn * 32 + ((lane >> 4) & 1) * 8 + (lane & 7)) * ROWP +
                                    ((lane >> 3) & 1) * 16);

#define LOAD_CHUNK(cidx, stgi) do {                                        \
    int k0 = (cidx) * 64;                                                  \
    uint32_t s0a = sb + (stgi) * STAGE_B;                                  \
    CP16(s0a + dd[0], Aa + ar[0] + k0);                                    \
    CP16(s0a + dd[1], Aa + ar[1] + k0);                                    \
    CP16(s0a + dd[2], Aa + ar[2] + k0);                                    \
    CP16(s0a + dd[3], Aa + ar[3] + k0);                                    \
    CP16(s0a + TILE_B + dd[0], Wh + wr[0] + k0);                           \
    CP16(s0a + TILE_B + dd[1], Wh + wr[1] + k0);                           \
    CP16(s0a + TILE_B + dd[2], Wh + wr[2] + k0);                           \
    CP16(s0a + TILE_B + dd[3], Wh + wr[3] + k0);                           \
    if (TP) {                                                              \
        CP16(s0a + 2 * TILE_B + dd[0], Wl + wr[0] + k0);                   \
        CP16(s0a + 2 * TILE_B + dd[1], Wl + wr[1] + k0);                   \
        CP16(s0a + 2 * TILE_B + dd[2], Wl + wr[2] + k0);                   \
        CP16(s0a + 2 * TILE_B + dd[3], Wl + wr[3] + k0);                   \
    }                                                                      \
    CP_COMMIT();                                                          \
} while (0)

    float acc[4][4][4] = {};

    LOAD_CHUNK(0, 0);

    for (int c = 0; c < 8; c++) {
        if (c) __syncthreads();          // prior compute on the stage LOAD will overwrite is done
        if (c < 7) LOAD_CHUNK(c + 1, (c + 1) & 1);
        if (c < 7) cp_wait<1>(); else cp_wait<0>();
        __syncthreads();                 // chunk-c data visible to all threads

        const uint32_t stg = sb + (c & 1) * STAGE_B;
        #pragma unroll
        for (int kk = 0; kk < 4; kk++) {
            uint32_t ah[4][4], bh[2][4], bl[2][4];
            #pragma unroll
            for (int mf = 0; mf < 4; mf++) {
                ldsm4(ah[mf][0], ah[mf][1], ah[mf][2], ah[mf][3],
                      stg + a_l + mf * 2304 + kk * 32);
            }
            #pragma unroll
            for (int p = 0; p < 2; p++) {
                uint32_t baddr = stg + TILE_B + b_l + p * 2304 + kk * 32;
                ldsm4(bh[p][0], bh[p][1], bh[p][2], bh[p][3], baddr);
                if (TP) ldsm4(bl[p][0], bl[p][1], bl[p][2], bl[p][3], baddr + TILE_B);
            }
            #pragma unroll
            for (int mf = 0; mf < 4; mf++)
                #pragma unroll
                for (int p = 0; p < 2; p++)
                    #pragma unroll
                    for (int q = 0; q < 2; q++) {
                        int nf = p * 2 + q;
                        mma16816(acc[mf][nf], ah[mf], &bh[p][2 * q]);
                        if (TP) mma16816(acc[mf][nf], ah[mf], &bl[p][2 * q]);
                    }
        }
    }
#undef LOAD_CHUNK

    // --- epilogue ---
    #pragma unroll
    for (int mf = 0; mf < 4; mf++) {
        #pragma unroll
        for (int half = 0; half < 2; half++) {
            int m = bm + wm * 64 + mf * 16 + qrow + half * 8;
            if (m >= M) continue;
            int b = 0, node = 0, p = 0;
            if (MODE == 2) {
                int two = 2 * np;
                b = m / two;
                int cl = m - b * two;
                node = 2 * s + 1 + cl;
                p = s + (cl >> 1);
            } else if (MODE == 3) {
                b = m / np;
                p = s + (m - b * np);
            }
            #pragma unroll
            for (int nf = 0; nf < 4; nf++) {
                int n = bn + wn * 32 + nf * 8 + qcol;
                float2 v = make_float2(acc[mf][nf][half * 2], acc[mf][nf][half * 2 + 1]);
                if (MODE == 0) {
                    float2 bi = *(const float2*)(bias + n);
                    v.x += bi.x; v.y += bi.y;
                    *(float2*)(g_fe_iou + (size_t)m * F3 + n) = v;
                } else if (MODE == 1) {
                    float2 bi = *(const float2*)(bias + n);
                    v.x += bi.x; v.y += bi.y;
                    *(float2*)(g_ff + (size_t)m * F_ + n) = v;
                } else if (MODE == 2) {
                    float2 ffv = *(const float2*)(g_ff + ((size_t)b * 255 + p) * F_ + n);
                    float2 cv  = *(const float2*)(g_c + ((size_t)b * NN + node) * F_ + n);
                    float2 o;
                    o.x = sigf(v.x + ffv.x) * cv.x;
                    o.y = sigf(v.y + ffv.y) * cv.y;
                    *(float2*)(g_fc + (size_t)m * F_ + n) = o;
                } else {
                    float2 fe = *(const float2*)(g_fe_iou + ((size_t)b * NN + p) * F3 + n);
                    v.x += fe.x; v.y += fe.y;
                    *(float2*)(g_iou + (size_t)m * F3 + n) = v;
                }
            }
        }
    }
}

// combined front GEMMs: fe_iou (12-wide tiles) then ff (4-wide tiles)
__global__ void __launch_bounds__(256, 2)
front_k(const float* __restrict__ b_iou, const float* __restrict__ b_f) {
    extern __shared__ char smem[];
    int bx = blockIdx.x;
    if (bx < 1536) {
        gemm_core<0>(smem, (bx / 12) * 128, (bx % 12) * 128, b_iou, 16352, 0, 0);
    } else {
        bx -= 1536;
        gemm_core<1>(smem, (bx >> 2) * 128, (bx & 3) * 128, b_f, 8160, 0, 0);
    }
}

// fused per-level kernel: fc blocks first, iou blocks after
__global__ void __launch_bounds__(256, 2)
level_k(int s, int np, int yF, int Mf, int Mi) {
    extern __shared__ char smem[];
    int bx = blockIdx.x;
    if (bx < 4 * yF) {
        gemm_core<2>(smem, (bx >> 2) * 128, (bx & 3) * 128, nullptr, Mf, s, np);
    } else {
        bx -= 4 * yF;
        gemm_core<3>(smem, (bx / 12) * 128, (bx % 12) * 128, nullptr, Mi, s, np);
    }
}

// ======================= gates (pair-fused with hsum) =======================
__global__ void leafpair_k() {
    int idx = blockIdx.x * blockDim.x + threadIdx.x;  // 32*128*512
    int f = idx & 511, r = idx >> 9;   // r = b*128 + j
    int b = r >> 7, j = r & 127;
    float hs = 0.f;
    #pragma unroll
    for (int t = 0; t < 2; t++) {
        int node = 255 + 2 * j + t;
        size_t io = ((size_t)b * NN + node) * F3;
        float cn = sigf(g_fe_iou[io + f]) * fmaxf(g_fe_iou[io + 1024 + f], 0.f);
        float hn = sigf(g_fe_iou[io + 512 + f]) * tanhf(cn);
        size_t ho = ((size_t)b * NN + node) * F_ + f;
        g_c[ho] = cn;
        g_h[ho] = hn;
        g_ha[ho] = __float2half(hn);
        hs += hn;
    }
    g_hs[(size_t)r * F_ + f] = __float2half(hs);
}

__global__ void gatepair_k(int s, int np, int total) {
    int idx = blockIdx.x * blockDim.x + threadIdx.x;
    if (idx >= total) return;
    int f = idx & 511, r = idx >> 9;   // r = b*half + j
    int half = np >> 1;
    int b = r / half, j = r - b * half;
    float hs = 0.f;
    #pragma unroll
    for (int t = 0; t < 2; t++) {
        int pl = 2 * j + t;
        int rr = b * np + pl;
        int node = s + pl;
        size_t io = (size_t)rr * F3;
        float csum = g_fc[(size_t)(2 * rr) * F_ + f] + g_fc[(size_t)(2 * rr + 1) * F_ + f];
        float cn = sigf(g_iou[io + f]) * fmaxf(g_iou[io + 1024 + f], 0.f) + csum;
        float hn = sigf(g_iou[io + 512 + f]) * tanhf(cn);
        size_t ho = ((size_t)b * NN + node) * F_ + f;
        g_c[ho] = cn;
        g_h[ho] = hn;
        g_ha[ho] = __float2half(hn);
        hs += hn;
    }
    g_hs[(size_t)r * F_ + f] = __float2half(hs);
}

// ======================= readout (root gate fused into rscore) =======================
__global__ void rscore_k() {
    int gw = (blockIdx.x * blockDim.x + threadIdx.x) >> 5;
    int lane = threadIdx.x & 31;
    if (gw >= B_ * NN) return;
    int b = gw / NN;
    int i = gw - b * NN;
    float s = 0.f;
    if (i == 0) {
        // root gate: level 8 left g_iou rows r=b (np=1) and g_fc rows 2b, 2b+1
        size_t io = (size_t)b * F3;
        for (int f = lane; f < F_; f += 32) {
            float csum = g_fc[(size_t)(2 * b) * F_ + f] + g_fc[(size_t)(2 * b + 1) * F_ + f];
            float cn = sigf(g_iou[io + f]) * fmaxf(g_iou[io + 1024 + f], 0.f) + csum;
            float hn = sigf(g_iou[io + 512 + f]) * tanhf(cn);
            g_h[(size_t)b * NN * F_ + f] = hn;   // node 0 row, read by final_k
            s += hn * g_eforw[b * F_ + f];
        }
    } else {
        const float4* hp = (const float4*)(g_h + (size_t)gw * F_);
        const float4* ep = (const float4*)(g_eforw + b * F_);
        for (int t = lane; t < 128; t += 32) {
            float4 h = hp[t], e = ep[t];
            s += h.x * e.x + h.y * e.y + h.z * e.z + h.w * e.w;
        }
    }
    #pragma unroll
    for (int off = 16; off; off >>= 1) s += __shfl_xor_sync(0xffffffffu, s, off);
    if (!lane) g_r[b * 512 + i] = s;
}

__global__ void final_k(float* __restrict__ out) {
    __shared__ float red[128];
    __shared__ float pr[NN];
    int b = blockIdx.y, tid = threadIdx.x;
    float mx = -1e30f;
    for (int i = tid; i < NN; i += 128) mx = fmaxf(mx, g_r[b * 512 + i]);
    red[tid] = mx;
    __syncthreads();
    for (int o = 64; o; o >>= 1) {
        if (tid < o) red[tid] = fmaxf(red[tid], red[tid + o]);
        __syncthreads();
    }
    mx = red[0];
    __syncthreads();
    float sm = 0.f;
    for (int i = tid; i < NN; i += 128) {
        float e = expf(g_r[b * 512 + i] - mx);
        pr[i] = e;
        sm += e;
    }
    red[tid] = sm;
    __syncthreads();
    for (int o = 64; o; o >>= 1) {
        if (tid < o) red[tid] += red[tid + o];
        __syncthreads();
    }
    float inv = 1.f / red[0];
    __syncthreads();
    int f = blockIdx.x * 128 + tid;
    float acc = 0.f;
    for (int i = 0; i < NN; i++) acc += pr[i] * g_h[((size_t)b * NN + i) * F_ + f];
    out[b * F_ + f] = acc * inv;
}

// ======================= launcher =======================
extern "C" void kernel_launch(void* const* d_in, const int* in_sizes, int n_in,
                              void* d_out, int out_size) {
    const float* feat     = (const float*)d_in[0];
    const float* eh       = (const float*)d_in[5];
    const float* Wn       = (const float*)d_in[6];
    const float* Wf       = (const float*)d_in[7];
    const float* W_iou    = (const float*)d_in[8];
    const float* W_fe_iou = (const float*)d_in[9];
    const float* b_fe_iou = (const float*)d_in[10];
    const float* W_f      = (const float*)d_in[11];
    const float* W_fe_f   = (const float*)d_in[12];
    const float* b_fe_f   = (const float*)d_in[13];
    float* out = (float*)d_out;

    static bool attr_done = false;
    if (!attr_done) {
        cudaFuncSetAttribute(front_k, cudaFuncAttributeMaxDynamicSharedMemorySize, SMEM_TOT);
        cudaFuncSetAttribute(level_k, cudaFuncAttributeMaxDynamicSharedMemorySize, SMEM_TOT);
        attr_done = true;
    }

    prolog_k<<<8192 + 4096, 256>>>(W_fe_iou, W_fe_f, W_f, W_iou, eh, Wn, Wf);
    scores_k<<<2044, 256>>>(feat);
    feat2_k<<<dim3(8, B_, 4), 128>>>(feat);

    // fe_iou (M=16352,N=1536) + ff (M=8160,N=512) in one launch
    front_k<<<1536 + 256, 256, SMEM_TOT>>>(b_fe_iou, b_fe_f);

    leafpair_k<<<(B_ * 128 * F_) / 256, 256>>>();

    for (int n = 1; n <= 8; n++) {
        int np = 1 << (8 - n);
        int s = np - 1;
        int Mf = B_ * 2 * np;
        int Mi = B_ * np;
        int yF = (Mf + 127) / 128;
        int yI = (Mi + 127) / 128;
        level_k<<<4 * yF + 12 * yI, 256, SMEM_TOT>>>(s, np, yF, Mf, Mi);
        if (np > 1) {
            int total = B_ * (np >> 1) * F_;
            gatepair_k<<<(total + 255) / 256, 256>>>(s, np, total);
        }
        // np == 1: root gate is fused into rscore_k
    }

    rscore_k<<<2044, 256>>>();
    final_k<<<dim3(4, B_), 128>>>(out);
}